// round 9
// baseline (speedup 1.0000x reference)
#include <cuda_runtime.h>
#include <stdint.h>

// Problem constants (fixed by the reference: B=64, T=2048, D=64, V=100000)
#define BB 64
#define TT 2048
#define DD 64
#define NROWS (4 * BB)          // 4 features x 64 batches = beta rows/blocks
#define BT (BB * TT)            // 131072
#define NEMITBLK (BT / 8)       // 16384 emit blocks (8 warps each)

// Output layout (floats), tuple flattened in order:
//   features [B,T,256] @ 0
//   times    [B,T]     @ BT*256
//   delta    [B,T,256] @ BT*256 + BT
//   mask     [B,T,256] @ BT*256 + BT + BT*256
#define OFF_TIMES  (BT * 256)                 // 33554432
#define OFF_DELTA  (OFF_TIMES + BT)           // 33685504
#define OFF_MASK   (OFF_DELTA + BT * 256)     // 67239936

// Scratch for the beta recurrence results: [4][B][T]
__device__ float g_beta[4 * BT];
// Producer/consumer handshake (self-resetting each launch for graph replays)
__device__ int g_done = 0;   // beta blocks completed
__device__ int g_ack  = 0;   // emit blocks completed

// ---------------------------------------------------------------------------
// Per-element recurrence coefficients: x_t = a*x_{t-1} + c.
// ---------------------------------------------------------------------------
__device__ __forceinline__ void load_elem(int f, int t, const float* tr,
                                          const int* c1r, const int* c2r,
                                          const float* n1r, const float* n2r,
                                          float& a, float& c)
{
    if (t == 0) { a = 0.0f; c = 0.0f; return; }
    const float tc = tr[t];
    const float dt = tc - tr[t - 1];
    const float p  = (tc != -1.0f) ? 1.0f : 0.0f;
    float m;
    if (f == 0)      { const int   v = __ldg(c1r + t - 1); m = (v != 0 && v != -1) ? 1.0f : 0.0f; }
    else if (f == 1) { const int   v = __ldg(c2r + t - 1); m = (v != 0 && v != -1) ? 1.0f : 0.0f; }
    else if (f == 2) { const float v = __ldg(n1r + t - 1); m = (v != 0.0f && v != -1.0f) ? 1.0f : 0.0f; }
    else             { const float v = __ldg(n2r + t - 1); m = (v != 0.0f && v != -1.0f) ? 1.0f : 0.0f; }
    a = m * p;
    c = dt * p;
}

// ---------------------------------------------------------------------------
// Fused kernel.
//   blocks [0, NROWS):              beta scan rows (256 thr, 8 elems/thread)
//   blocks [NROWS, NROWS+NEMITBLK): emit (8 warps, one (b,t) per warp)
// Emit defers the beta-dependent delta stores until g_done == NROWS.
// ---------------------------------------------------------------------------
__global__ __launch_bounds__(256) void fused_kernel(
    const int*   __restrict__ cat1,
    const int*   __restrict__ cat2,
    const float* __restrict__ num1,
    const float* __restrict__ num2,
    const float* __restrict__ times,
    const float* __restrict__ E1,
    const float* __restrict__ E2,
    const float* __restrict__ w1,
    const float* __restrict__ b1,
    const float* __restrict__ w2,
    const float* __restrict__ b2,
    float* __restrict__ out)
{
    const int tid  = threadIdx.x;
    const int lane = tid & 31;

    if (blockIdx.x < NROWS) {
        // =================== beta scan (one row per block) ===================
        const int row = blockIdx.x;
        const int f   = row >> 6;
        const int b   = row & 63;
        const int wid = tid >> 5;          // 0..7

        __shared__ float sA[8], sC[8];

        const float* tr  = times + b * TT;
        const int*   c1r = cat1  + b * TT;
        const int*   c2r = cat2  + b * TT;
        const float* n1r = num1  + b * TT;
        const float* n2r = num2  + b * TT;

        const int t0 = tid * 8;
        float a[8], c[8];
        #pragma unroll
        for (int k = 0; k < 8; ++k)
            load_elem(f, t0 + k, tr, c1r, c2r, n1r, n2r, a[k], c[k]);

        // Sequential composition of this thread's 8 elements
        float A = a[0], C = c[0];
        #pragma unroll
        for (int k = 1; k < 8; ++k) { C = c[k] + a[k] * C; A = a[k] * A; }

        // Warp inclusive scan of thread-compositions
        #pragma unroll
        for (int off = 1; off < 32; off <<= 1) {
            const float Ap = __shfl_up_sync(0xffffffffu, A, off);
            const float Cp = __shfl_up_sync(0xffffffffu, C, off);
            if (lane >= off) { C = C + A * Cp; A = A * Ap; }
        }
        if (lane == 31) { sA[wid] = A; sC[wid] = C; }
        __syncthreads();

        // Tiny sequential exclusive scan over the 8 warp aggregates
        if (tid == 0) {
            float Ae = 1.0f, Ce = 0.0f;
            #pragma unroll
            for (int i = 0; i < 8; ++i) {
                const float Ai = sA[i], Ci = sC[i];
                sA[i] = Ae; sC[i] = Ce;
                Ce = Ci + Ai * Ce;
                Ae = Ai * Ae;
            }
        }
        __syncthreads();

        // Thread-exclusive within warp
        float Ax = __shfl_up_sync(0xffffffffu, A, 1);
        float Cx = __shfl_up_sync(0xffffffffu, C, 1);
        if (lane == 0) { Ax = 1.0f; Cx = 0.0f; }

        // x before this thread's span (x starts at 0 -> value = C terms only)
        const float xw   = sC[wid];
        float x = Cx + Ax * xw;

        float buf[8];
        #pragma unroll
        for (int k = 0; k < 8; ++k) { x = c[k] + a[k] * x; buf[k] = x; }

        float4* br = reinterpret_cast<float4*>(g_beta + (size_t)row * TT + t0);
        br[0] = make_float4(buf[0], buf[1], buf[2], buf[3]);
        br[1] = make_float4(buf[4], buf[5], buf[6], buf[7]);

        // Release: make g_beta visible, then signal
        __threadfence();
        __syncthreads();
        if (tid == 0) atomicAdd(&g_done, 1);
        return;
    }

    // ======================= emit (one (b,t) per warp) =======================
    const int gw = (blockIdx.x - NROWS) * 8 + (tid >> 5);

    const bool lo = (lane < 16);
    const int  sl = lo ? lane : (lane - 16);   // sub-lane within 16

    // --- batch scalar loads ---
    const int   c1 = __ldg(cat1 + gw);
    const int   c2 = __ldg(cat2 + gw);
    const float n1 = __ldg(num1 + gw);
    const float n2 = __ldg(num2 + gw);
    const float tm = __ldg(times + gw);

    // --- feature gathers / numeric embeds ---
    const float4* e1row = reinterpret_cast<const float4*>(E1 + (size_t)c1 * DD);
    const float4* e2row = reinterpret_cast<const float4*>(E2 + (size_t)c2 * DD);
    const float4* src0  = lo ? (e1row + sl) : (e2row + sl);
    const float4  v0    = __ldg(src0);

    const float4* wsrc = lo ? (reinterpret_cast<const float4*>(w1) + sl)
                            : (reinterpret_cast<const float4*>(w2) + sl);
    const float4* osrc = lo ? (reinterpret_cast<const float4*>(b1) + sl)
                            : (reinterpret_cast<const float4*>(b2) + sl);
    const float4 wv = __ldg(wsrc);
    const float4 ov = __ldg(osrc);
    const float  nn = lo ? n1 : n2;
    const float4 v1 = make_float4(fmaf(nn, wv.x, ov.x), fmaf(nn, wv.y, ov.y),
                                  fmaf(nn, wv.z, ov.z), fmaf(nn, wv.w, ov.w));

    // --- mask lane values ---
    const float mk0 = (c1 != 0 && c1 != -1)       ? 1.0f : 0.0f;
    const float mk1 = (c2 != 0 && c2 != -1)       ? 1.0f : 0.0f;
    const float mk2 = (n1 != 0.0f && n1 != -1.0f) ? 1.0f : 0.0f;
    const float mk3 = (n2 != 0.0f && n2 != -1.0f) ? 1.0f : 0.0f;
    const float mv0 = lo ? mk0 : mk1;
    const float mv1 = lo ? mk2 : mk3;

    float4* feat4  = reinterpret_cast<float4*>(out) + (size_t)gw * 64;
    float4* delta4 = reinterpret_cast<float4*>(out + OFF_DELTA) + (size_t)gw * 64;
    float4* mask4  = reinterpret_cast<float4*>(out + OFF_MASK)  + (size_t)gw * 64;

    // --- beta-independent stores first (features, mask, times) ---
    __stcs(feat4 + lane,      v0);
    __stcs(feat4 + lane + 32, v1);
    __stcs(mask4 + lane,      make_float4(mv0, mv0, mv0, mv0));
    __stcs(mask4 + lane + 32, make_float4(mv1, mv1, mv1, mv1));
    if (lane == 0) {
        __stcs(out + OFF_TIMES + gw, tm);
    }

    // --- wait for beta producers (acquire) ---
    if (tid == 0) {
        while (atomicAdd(&g_done, 0) < NROWS) { }
        __threadfence();
    }
    __syncthreads();

    // --- delta stores ---
    const float be0 = g_beta[0 * BT + gw];
    const float be1 = g_beta[1 * BT + gw];
    const float be2 = g_beta[2 * BT + gw];
    const float be3 = g_beta[3 * BT + gw];
    const float bv0 = lo ? be0 : be1;
    const float bv1 = lo ? be2 : be3;

    __stcs(delta4 + lane,      make_float4(bv0, bv0, bv0, bv0));
    __stcs(delta4 + lane + 32, make_float4(bv1, bv1, bv1, bv1));

    // --- completion ack: last emit block resets counters for next replay ---
    __syncthreads();
    if (tid == 0) {
        const int v = atomicAdd(&g_ack, 1);
        if (v == NEMITBLK - 1) {
            g_done = 0;
            g_ack  = 0;
            __threadfence();
        }
    }
}

// ---------------------------------------------------------------------------
// Launch
// Inputs (metadata order): cat1, cat2, num1, num2, event_time, E1, E2,
//                          w1, b1, w2, b2
// ---------------------------------------------------------------------------
extern "C" void kernel_launch(void* const* d_in, const int* in_sizes, int n_in,
                              void* d_out, int out_size)
{
    const int*   cat1  = (const int*)  d_in[0];
    const int*   cat2  = (const int*)  d_in[1];
    const float* num1  = (const float*)d_in[2];
    const float* num2  = (const float*)d_in[3];
    const float* times = (const float*)d_in[4];
    const float* E1    = (const float*)d_in[5];
    const float* E2    = (const float*)d_in[6];
    const float* w1    = (const float*)d_in[7];
    const float* b1    = (const float*)d_in[8];
    const float* w2    = (const float*)d_in[9];
    const float* b2    = (const float*)d_in[10];
    float* out = (float*)d_out;

    // Single fused launch: 256 beta blocks + 16384 emit blocks
    fused_kernel<<<NROWS + NEMITBLK, 256>>>(cat1, cat2, num1, num2, times,
                                            E1, E2, w1, b1, w2, b2, out);
}

// round 10
// speedup vs baseline: 1.1743x; 1.1743x over previous
#include <cuda_runtime.h>
#include <stdint.h>

// Problem constants (fixed by the reference: B=64, T=2048, D=64, V=100000)
#define BB 64
#define TT 2048
#define DD 64
#define NROWS (4 * BB)          // 4 features x 64 batches
#define BT (BB * TT)            // 131072

// Output layout (floats), tuple flattened in order:
//   features [B,T,256] @ 0
//   times    [B,T]     @ BT*256
//   delta    [B,T,256] @ BT*256 + BT
//   mask     [B,T,256] @ BT*256 + BT + BT*256
#define OFF_TIMES  (BT * 256)                 // 33554432
#define OFF_DELTA  (OFF_TIMES + BT)           // 33685504
#define OFF_MASK   (OFF_DELTA + BT * 256)     // 67239936

// Scratch for the beta recurrence results: [4][B][T]
__device__ float g_beta[4 * BT];

// ---------------------------------------------------------------------------
// Kernel 1: beta linear-recurrence scan.
// x_t = a_t * x_{t-1} + c_t, a_t = m_{t-1}*p_t, c_t = dt_t*p_t, x_0 = 0.
// One 256-thread block per (f,b) row, 8 elems/thread, vectorized loads.
// ---------------------------------------------------------------------------
__global__ __launch_bounds__(256) void beta_scan_kernel(
    const int*   __restrict__ cat1,
    const int*   __restrict__ cat2,
    const float* __restrict__ num1,
    const float* __restrict__ num2,
    const float* __restrict__ times)
{
    const int row  = blockIdx.x;        // 0..255
    const int f    = row >> 6;          // 0..3
    const int b    = row & 63;          // 0..63
    const int tid  = threadIdx.x;       // 0..255
    const int lane = tid & 31;
    const int wid  = tid >> 5;          // 0..7

    __shared__ float sA[8], sC[8];

    const float* tr = times + b * TT;
    const int t0 = tid * 8;

    // ---- vectorized time loads: tv[0..7] = tr[t0..t0+7] ----
    const float4 ta = __ldg(reinterpret_cast<const float4*>(tr + t0));
    const float4 tb = __ldg(reinterpret_cast<const float4*>(tr + t0 + 4));
    float tv[8] = {ta.x, ta.y, ta.z, ta.w, tb.x, tb.y, tb.z, tb.w};

    // tr[t0-1]: previous lane's tv[7]; lane 0 loads scalar (block-uniform safe)
    float tprev = __shfl_up_sync(0xffffffffu, tv[7], 1);
    if (lane == 0) tprev = (t0 > 0) ? __ldg(tr + t0 - 1) : 0.0f;

    // ---- feature mask values m[k] for feat[t0+k-1], k=0..7 ----
    float m[8];
    if (f < 2) {
        const int* cr = (f == 0 ? cat1 : cat2) + b * TT;
        const int4 va = __ldg(reinterpret_cast<const int4*>(cr + t0));
        const int4 vb = __ldg(reinterpret_cast<const int4*>(cr + t0 + 4));
        int fv[8] = {va.x, va.y, va.z, va.w, vb.x, vb.y, vb.z, vb.w};
        int fprev = __shfl_up_sync(0xffffffffu, fv[7], 1);
        if (lane == 0) fprev = (t0 > 0) ? __ldg(cr + t0 - 1) : 0;
        m[0] = (fprev != 0 && fprev != -1) ? 1.0f : 0.0f;
        #pragma unroll
        for (int k = 1; k < 8; ++k)
            m[k] = (fv[k - 1] != 0 && fv[k - 1] != -1) ? 1.0f : 0.0f;
    } else {
        const float* nr = (f == 2 ? num1 : num2) + b * TT;
        const float4 va = __ldg(reinterpret_cast<const float4*>(nr + t0));
        const float4 vb = __ldg(reinterpret_cast<const float4*>(nr + t0 + 4));
        float fv[8] = {va.x, va.y, va.z, va.w, vb.x, vb.y, vb.z, vb.w};
        float fprev = __shfl_up_sync(0xffffffffu, fv[7], 1);
        if (lane == 0) fprev = (t0 > 0) ? __ldg(nr + t0 - 1) : 0.0f;
        m[0] = (fprev != 0.0f && fprev != -1.0f) ? 1.0f : 0.0f;
        #pragma unroll
        for (int k = 1; k < 8; ++k)
            m[k] = (fv[k - 1] != 0.0f && fv[k - 1] != -1.0f) ? 1.0f : 0.0f;
    }

    // ---- per-element coefficients ----
    float a[8], c[8];
    #pragma unroll
    for (int k = 0; k < 8; ++k) {
        const float tkm1 = (k == 0) ? tprev : tv[k - 1];
        const float p  = (tv[k] != -1.0f) ? 1.0f : 0.0f;
        a[k] = m[k] * p;
        c[k] = (tv[k] - tkm1) * p;
    }
    if (t0 == 0) { a[0] = 0.0f; c[0] = 0.0f; }   // beta[0] = 0

    // ---- sequential composition of this thread's 8 elements ----
    float A = a[0], C = c[0];
    #pragma unroll
    for (int k = 1; k < 8; ++k) { C = c[k] + a[k] * C; A = a[k] * A; }

    // ---- warp inclusive scan of thread-compositions ----
    #pragma unroll
    for (int off = 1; off < 32; off <<= 1) {
        const float Ap = __shfl_up_sync(0xffffffffu, A, off);
        const float Cp = __shfl_up_sync(0xffffffffu, C, off);
        if (lane >= off) { C = C + A * Cp; A = A * Ap; }
    }
    if (lane == 31) { sA[wid] = A; sC[wid] = C; }
    __syncthreads();

    // ---- tiny serial exclusive scan over 8 warp aggregates ----
    if (tid == 0) {
        float Ae = 1.0f, Ce = 0.0f;
        #pragma unroll
        for (int i = 0; i < 8; ++i) {
            const float Ai = sA[i], Ci = sC[i];
            sA[i] = Ae; sC[i] = Ce;
            Ce = Ci + Ai * Ce;
            Ae = Ai * Ae;
        }
    }
    __syncthreads();

    // ---- thread-exclusive prefix (x starts at 0 -> only C terms survive) ----
    float Ax = __shfl_up_sync(0xffffffffu, A, 1);
    float Cx = __shfl_up_sync(0xffffffffu, C, 1);
    if (lane == 0) { Ax = 1.0f; Cx = 0.0f; }
    float x = Cx + Ax * sC[wid];

    // ---- apply elementwise, store vectorized ----
    float buf[8];
    #pragma unroll
    for (int k = 0; k < 8; ++k) { x = c[k] + a[k] * x; buf[k] = x; }

    float4* br = reinterpret_cast<float4*>(g_beta + (size_t)row * TT + t0);
    br[0] = make_float4(buf[0], buf[1], buf[2], buf[3]);
    br[1] = make_float4(buf[4], buf[5], buf[6], buf[7]);
}

// ---------------------------------------------------------------------------
// Kernel 2: emit all outputs (exact R6 — best measured config).
// One warp per (b,t), branchless lane-selects, loads batched ahead of the
// store burst, __stcs (evict-first) on all output stores.
// ---------------------------------------------------------------------------
__global__ void emit_kernel(const int*   __restrict__ cat1,
                            const int*   __restrict__ cat2,
                            const float* __restrict__ num1,
                            const float* __restrict__ num2,
                            const float* __restrict__ times,
                            const float* __restrict__ E1,
                            const float* __restrict__ E2,
                            const float* __restrict__ w1,
                            const float* __restrict__ b1,
                            const float* __restrict__ w2,
                            const float* __restrict__ b2,
                            float* __restrict__ out)
{
    const int gw   = blockIdx.x * (blockDim.x >> 5) + (threadIdx.x >> 5); // (b,t)
    const int lane = threadIdx.x & 31;

    const bool lo = (lane < 16);
    const int  sl = lo ? lane : (lane - 16);   // sub-lane within 16

    // --- batch all scalar loads (independent, high MLP) ---
    const int   c1 = __ldg(cat1 + gw);
    const int   c2 = __ldg(cat2 + gw);
    const float n1 = __ldg(num1 + gw);
    const float n2 = __ldg(num2 + gw);
    const float tm = __ldg(times + gw);

    const float be0 = g_beta[0 * BT + gw];
    const float be1 = g_beta[1 * BT + gw];
    const float be2 = g_beta[2 * BT + gw];
    const float be3 = g_beta[3 * BT + gw];

    // --- half 0 gather: lanes 0-15 -> E1 row, lanes 16-31 -> E2 row ---
    const float4* e1row = reinterpret_cast<const float4*>(E1 + (size_t)c1 * DD);
    const float4* e2row = reinterpret_cast<const float4*>(E2 + (size_t)c2 * DD);
    const float4* src0  = lo ? (e1row + sl) : (e2row + sl);
    const float4  v0    = __ldg(src0);

    // --- half 1: lanes 0-15 -> n1*w1+b1, lanes 16-31 -> n2*w2+b2 ---
    const float4* wsrc = lo ? (reinterpret_cast<const float4*>(w1) + sl)
                            : (reinterpret_cast<const float4*>(w2) + sl);
    const float4* osrc = lo ? (reinterpret_cast<const float4*>(b1) + sl)
                            : (reinterpret_cast<const float4*>(b2) + sl);
    const float4 wv = __ldg(wsrc);
    const float4 ov = __ldg(osrc);
    const float  nn = lo ? n1 : n2;
    const float4 v1 = make_float4(fmaf(nn, wv.x, ov.x), fmaf(nn, wv.y, ov.y),
                                  fmaf(nn, wv.z, ov.z), fmaf(nn, wv.w, ov.w));

    // --- delta / mask lane values (SELs, no branches) ---
    const float mk0 = (c1 != 0 && c1 != -1)       ? 1.0f : 0.0f;
    const float mk1 = (c2 != 0 && c2 != -1)       ? 1.0f : 0.0f;
    const float mk2 = (n1 != 0.0f && n1 != -1.0f) ? 1.0f : 0.0f;
    const float mk3 = (n2 != 0.0f && n2 != -1.0f) ? 1.0f : 0.0f;

    const float bv0 = lo ? be0 : be1;   // half 0: features 0,1
    const float bv1 = lo ? be2 : be3;   // half 1: features 2,3
    const float mv0 = lo ? mk0 : mk1;
    const float mv1 = lo ? mk2 : mk3;

    // --- store burst (all data ready; evict-first STG.128 streams) ---
    float4* feat4  = reinterpret_cast<float4*>(out) + (size_t)gw * 64;
    float4* delta4 = reinterpret_cast<float4*>(out + OFF_DELTA) + (size_t)gw * 64;
    float4* mask4  = reinterpret_cast<float4*>(out + OFF_MASK)  + (size_t)gw * 64;

    __stcs(feat4 + lane,       v0);
    __stcs(feat4 + lane + 32,  v1);
    __stcs(delta4 + lane,      make_float4(bv0, bv0, bv0, bv0));
    __stcs(delta4 + lane + 32, make_float4(bv1, bv1, bv1, bv1));
    __stcs(mask4 + lane,       make_float4(mv0, mv0, mv0, mv0));
    __stcs(mask4 + lane + 32,  make_float4(mv1, mv1, mv1, mv1));

    if (lane == 0) {
        __stcs(out + OFF_TIMES + gw, tm);
    }
}

// ---------------------------------------------------------------------------
// Launch
// Inputs (metadata order): cat1, cat2, num1, num2, event_time, E1, E2,
//                          w1, b1, w2, b2
// ---------------------------------------------------------------------------
extern "C" void kernel_launch(void* const* d_in, const int* in_sizes, int n_in,
                              void* d_out, int out_size)
{
    const int*   cat1  = (const int*)  d_in[0];
    const int*   cat2  = (const int*)  d_in[1];
    const float* num1  = (const float*)d_in[2];
    const float* num2  = (const float*)d_in[3];
    const float* times = (const float*)d_in[4];
    const float* E1    = (const float*)d_in[5];
    const float* E2    = (const float*)d_in[6];
    const float* w1    = (const float*)d_in[7];
    const float* b1    = (const float*)d_in[8];
    const float* w2    = (const float*)d_in[9];
    const float* b2    = (const float*)d_in[10];
    float* out = (float*)d_out;

    // Kernel 1: one 256-thread block per (f,b) row, vectorized scan
    beta_scan_kernel<<<NROWS, 256>>>(cat1, cat2, num1, num2, times);

    // Kernel 2: one warp per (b,t): 131072 warps, 8 warps/block (exact grid)
    emit_kernel<<<BT / 8, 256>>>(cat1, cat2, num1, num2, times,
                                 E1, E2, w1, b1, w2, b2, out);
}